// round 15
// baseline (speedup 1.0000x reference)
#include <cuda_runtime.h>
#include <cuda_fp16.h>
#include <cstdint>

// ---------------------------------------------------------------------------
// TransformerBlock B=8,T=1024,E=1024,H=16,HD=64,HID=4096 fp32.
// R14: GEMM widened to 128x256 CTA tile (8 warps x 64x64, GBK=32, 4-stage
// cp.async) -> 2x MMA-per-ldmatrix density. Flash/LN/transpose unchanged
// from R13b (885us).
// ---------------------------------------------------------------------------

#define RROWS 8192
#define EDIM  1024
#define HEADS 16
#define HD    64
#define HID   4096
#define TSEQ  1024
#define BATCH 8

__device__ __half g_xn  [RROWS * EDIM];
__device__ __half g_qkv [RROWS * 3 * EDIM];
__device__ __half g_ycat[RROWS * EDIM];
__device__ __half g_h   [RROWS * HID];
__device__ __half g_wh  [12582912];   // transposed fp16 weights

#define WR_QKV  0            // [3072][1024]
#define WR_PROJ 3145728      // [1024][1024]
#define WR_FC   4194304      // [4096][1024]
#define WR_OUT  8388608      // [1024][4096]

__device__ __forceinline__ float gelu_tanh(float x) {
    float x3 = x * x * x;
    return 0.5f * x * (1.0f + tanhf(0.7978845608028654f * (x + 0.044715f * x3)));
}
__device__ __forceinline__ void cp_async16(void* smem_dst, const void* gsrc) {
    uint32_t d = (uint32_t)__cvta_generic_to_shared(smem_dst);
    asm volatile("cp.async.cg.shared.global [%0], [%1], 16;\n" :: "r"(d), "l"(gsrc));
}
__device__ __forceinline__ void cp_commit() { asm volatile("cp.async.commit_group;\n"); }
template <int N>
__device__ __forceinline__ void cp_wait() { asm volatile("cp.async.wait_group %0;\n" :: "n"(N)); }

// m16n8k16 fp16 MMA, fp32 accumulate.
__device__ __forceinline__ void mma_f16(float* c, const uint32_t* a, const uint32_t* b) {
    asm volatile(
        "mma.sync.aligned.m16n8k16.row.col.f32.f16.f16.f32 "
        "{%0,%1,%2,%3}, {%4,%5,%6,%7}, {%8,%9}, {%0,%1,%2,%3};"
        : "+f"(c[0]), "+f"(c[1]), "+f"(c[2]), "+f"(c[3])
        : "r"(a[0]), "r"(a[1]), "r"(a[2]), "r"(a[3]), "r"(b[0]), "r"(b[1]));
}

__device__ __forceinline__ void ldmatrix_x4(uint32_t& r0, uint32_t& r1, uint32_t& r2,
                                            uint32_t& r3, uint32_t saddr) {
    asm volatile("ldmatrix.sync.aligned.m8n8.x4.shared.b16 {%0,%1,%2,%3}, [%4];"
                 : "=r"(r0), "=r"(r1), "=r"(r2), "=r"(r3) : "r"(saddr));
}
__device__ __forceinline__ void ldmatrix_x2(uint32_t& r0, uint32_t& r1, uint32_t saddr) {
    asm volatile("ldmatrix.sync.aligned.m8n8.x2.shared.b16 {%0,%1}, [%2];"
                 : "=r"(r0), "=r"(r1) : "r"(saddr));
}
__device__ __forceinline__ void ldmatrix_x2_trans(uint32_t& r0, uint32_t& r1, uint32_t saddr) {
    asm volatile("ldmatrix.sync.aligned.m8n8.x2.trans.shared.b16 {%0,%1}, [%2];"
                 : "=r"(r0), "=r"(r1) : "r"(saddr));
}

// ---------------------------------------------------------------------------
// Weight transpose + fp16 convert:  WT[n][k] = half(W[k][n]).  in: [K][N].
// ---------------------------------------------------------------------------
__global__ void transpose_half(const float* __restrict__ in, __half* __restrict__ outp,
                               int K, int N) {
    __shared__ float t[32][33];
    const int n0 = blockIdx.x * 32, k0 = blockIdx.y * 32;
    const int tx = threadIdx.x, ty = threadIdx.y;
    #pragma unroll
    for (int j = 0; j < 32; j += 8)
        t[ty + j][tx] = in[(long long)(k0 + ty + j) * N + n0 + tx];
    __syncthreads();
    #pragma unroll
    for (int j = 0; j < 32; j += 8)
        outp[(long long)(n0 + ty + j) * K + k0 + tx] = __float2half(t[tx][ty + j]);
}

// ---------------------------------------------------------------------------
// LayerNorm: one block (256 threads) per 1024-col row; fp32 in, fp16 out.
// ---------------------------------------------------------------------------
__global__ void ln_kernel(const float* __restrict__ x,
                          const float* __restrict__ g,
                          const float* __restrict__ b,
                          __half* __restrict__ out) {
    __shared__ float red[8];
    const long long row = blockIdx.x;
    const int t = threadIdx.x;
    float4 v = ((const float4*)(x + row * EDIM))[t];

    float s = v.x + v.y + v.z + v.w;
    #pragma unroll
    for (int o = 16; o; o >>= 1) s += __shfl_xor_sync(~0u, s, o);
    if ((t & 31) == 0) red[t >> 5] = s;
    __syncthreads();
    if (t < 8) {
        s = red[t];
        #pragma unroll
        for (int o = 4; o; o >>= 1) s += __shfl_xor_sync(0xffu, s, o);
        if (t == 0) red[0] = s;
    }
    __syncthreads();
    const float mean = red[0] * (1.0f / EDIM);

    float dx = v.x - mean, dy = v.y - mean, dz = v.z - mean, dw = v.w - mean;
    float q = dx * dx + dy * dy + dz * dz + dw * dw;
    #pragma unroll
    for (int o = 16; o; o >>= 1) q += __shfl_xor_sync(~0u, q, o);
    __syncthreads();
    if ((t & 31) == 0) red[t >> 5] = q;
    __syncthreads();
    if (t < 8) {
        q = red[t];
        #pragma unroll
        for (int o = 4; o; o >>= 1) q += __shfl_xor_sync(0xffu, q, o);
        if (t == 0) red[0] = q;
    }
    __syncthreads();
    const float rstd = rsqrtf(red[0] * (1.0f / EDIM) + 1e-5f);

    const float4 gg = ((const float4*)g)[t];
    const float4 bb = ((const float4*)b)[t];
    half2 h0 = __floats2half2_rn(dx * rstd * gg.x + bb.x, dy * rstd * gg.y + bb.y);
    half2 h1 = __floats2half2_rn(dz * rstd * gg.z + bb.z, dw * rstd * gg.w + bb.w);
    half2* op = (half2*)(out + row * EDIM + t * 4);
    op[0] = h0; op[1] = h1;
}

// ---------------------------------------------------------------------------
// Flash attention fp16, non-causal — unchanged from R13b.
// ---------------------------------------------------------------------------
#define QSTR 72   // halves per row (64 + 8 pad)
#define FL_QOFF 0
#define FL_KOFF (256 * QSTR)
#define FL_VOFF (FL_KOFF + 2 * 64 * QSTR)
#define FL_POFF (FL_VOFF + 2 * 64 * QSTR)
#define FL_SMEM_H (FL_POFF + 256 * QSTR)

__global__ void __launch_bounds__(256)
flash_kernel(const __half* __restrict__ qkv, __half* __restrict__ ycat) {
    extern __shared__ __half sh[];
    __half* Qsm = sh + FL_QOFF;
    __half* Psm = sh + FL_POFF;

    const int tid  = threadIdx.x;
    const int lane = tid & 31;
    const int warp = tid >> 5;
    const int lr = lane >> 2;
    const int lc = lane & 3;
    const int q0 = blockIdx.x * 256;
    const int h  = blockIdx.y;
    const int b  = blockIdx.z;
    const int wm = warp * 32;

    const __half* qkvb = qkv + (long long)b * TSEQ * 3 * EDIM;
    const __half* Qg = qkvb + h * HD;
    const __half* Kg = qkvb + EDIM + h * HD;
    const __half* Vg = qkvb + 2 * EDIM + h * HD;

    const half2 qsc = __floats2half2_rn(0.125f, 0.125f);
    #pragma unroll
    for (int i = tid; i < 256 * 8; i += 256) {
        int r = i >> 3, ch = (i & 7) << 3;
        uint4 v = *(const uint4*)(Qg + (long long)(q0 + r) * 3 * EDIM + ch);
        half2* hv = (half2*)&v;
        hv[0] = __hmul2(hv[0], qsc); hv[1] = __hmul2(hv[1], qsc);
        hv[2] = __hmul2(hv[2], qsc); hv[3] = __hmul2(hv[3], qsc);
        *(uint4*)(Qsm + r * QSTR + ch) = v;
    }

    auto load_kv = [&](int j, int buf) {
        __half* Ks = sh + FL_KOFF + buf * 64 * QSTR;
        __half* Vs = sh + FL_VOFF + buf * 64 * QSTR;
        const __half* Kj = Kg + (long long)(j * 64) * 3 * EDIM;
        const __half* Vj = Vg + (long long)(j * 64) * 3 * EDIM;
        #pragma unroll
        for (int i = tid; i < 64 * 8; i += 256) {
            int r = i >> 3, ch = (i & 7) << 3;
            cp_async16(Ks + r * QSTR + ch, Kj + (long long)r * 3 * EDIM + ch);
            cp_async16(Vs + r * QSTR + ch, Vj + (long long)r * 3 * EDIM + ch);
        }
        cp_commit();
    };

    load_kv(0, 0);
    __syncthreads();

    uint32_t qfr[4][2][4];
    #pragma unroll
    for (int ks = 0; ks < 4; ks++) {
        #pragma unroll
        for (int im = 0; im < 2; im++) {
            uint32_t sa = (uint32_t)__cvta_generic_to_shared(
                Qsm + (wm + im * 16 + (lane & 15)) * QSTR + ks * 16 + ((lane >> 4) << 3));
            ldmatrix_x4(qfr[ks][im][0], qfr[ks][im][1], qfr[ks][im][2], qfr[ks][im][3], sa);
        }
    }

    float o[2][8][4];
    float m[2][2], l[2][2];
    #pragma unroll
    for (int im = 0; im < 2; im++) {
        #pragma unroll
        for (int jn = 0; jn < 8; jn++)
            #pragma unroll
            for (int q = 0; q < 4; q++) o[im][jn][q] = 0.0f;
        m[im][0] = m[im][1] = -1e30f;
        l[im][0] = l[im][1] = 0.0f;
    }

    const int NT = TSEQ / 64;
    for (int j = 0; j < NT; j++) {
        const int buf = j & 1;
        if (j + 1 < NT) { load_kv(j + 1, buf ^ 1); cp_wait<1>(); }
        else           { cp_wait<0>(); }
        __syncthreads();

        const __half* Ks = sh + FL_KOFF + buf * 64 * QSTR;
        const __half* Vs = sh + FL_VOFF + buf * 64 * QSTR;

        float s[2][8][4];
        #pragma unroll
        for (int im = 0; im < 2; im++)
            #pragma unroll
            for (int jn = 0; jn < 8; jn++)
                #pragma unroll
                for (int q = 0; q < 4; q++) s[im][jn][q] = 0.0f;

        #pragma unroll
        for (int ks = 0; ks < 4; ks++) {
            #pragma unroll
            for (int jn = 0; jn < 8; jn++) {
                uint32_t bfr[2];
                uint32_t sb = (uint32_t)__cvta_generic_to_shared(
                    Ks + (jn * 8 + (lane & 7)) * QSTR + ks * 16 + (((lane >> 3) & 3) == 1 ? 8 : 0));
                ldmatrix_x2(bfr[0], bfr[1], sb);
                #pragma unroll
                for (int im = 0; im < 2; im++) mma_f16(s[im][jn], qfr[ks][im], bfr);
            }
        }

        #pragma unroll
        for (int im = 0; im < 2; im++) {
            #pragma unroll
            for (int hf = 0; hf < 2; hf++) {
                float mx = -1e30f;
                #pragma unroll
                for (int jn = 0; jn < 8; jn++)
                    mx = fmaxf(mx, fmaxf(s[im][jn][hf * 2], s[im][jn][hf * 2 + 1]));
                mx = fmaxf(mx, __shfl_xor_sync(~0u, mx, 1));
                mx = fmaxf(mx, __shfl_xor_sync(~0u, mx, 2));
                const float mnew = fmaxf(m[im][hf], mx);
                const float alpha = __expf(m[im][hf] - mnew);
                m[im][hf] = mnew;
                const int prow = wm + im * 16 + hf * 8 + lr;
                float sum = 0.0f;
                #pragma unroll
                for (int jn = 0; jn < 8; jn++) {
                    float p0 = __expf(s[im][jn][hf * 2]     - mnew);
                    float p1 = __expf(s[im][jn][hf * 2 + 1] - mnew);
                    sum += p0 + p1;
                    *(half2*)(Psm + prow * QSTR + jn * 8 + 2 * lc) = __floats2half2_rn(p0, p1);
                }
                sum += __shfl_xor_sync(~0u, sum, 1);
                sum += __shfl_xor_sync(~0u, sum, 2);
                l[im][hf] = l[im][hf] * alpha + sum;
                #pragma unroll
                for (int jn = 0; jn < 8; jn++) {
                    o[im][jn][hf * 2]     *= alpha;
                    o[im][jn][hf * 2 + 1] *= alpha;
                }
            }
        }
        __syncwarp();

        #pragma unroll
        for (int ks = 0; ks < 4; ks++) {
            uint32_t afr[2][4];
            #pragma unroll
            for (int im = 0; im < 2; im++) {
                uint32_t sa = (uint32_t)__cvta_generic_to_shared(
                    Psm + (wm + im * 16 + (lane & 15)) * QSTR + ks * 16 + ((lane >> 4) << 3));
                ldmatrix_x4(afr[im][0], afr[im][1], afr[im][2], afr[im][3], sa);
            }
            #pragma unroll
            for (int jn = 0; jn < 8; jn++) {
                uint32_t bfr[2];
                uint32_t sv = (uint32_t)__cvta_generic_to_shared(
                    Vs + (ks * 16 + (lane & 15)) * QSTR + jn * 8);
                ldmatrix_x2_trans(bfr[0], bfr[1], sv);
                #pragma unroll
                for (int im = 0; im < 2; im++) mma_f16(o[im][jn], afr[im], bfr);
            }
        }
        __syncthreads();
    }

    #pragma unroll
    for (int im = 0; im < 2; im++) {
        #pragma unroll
        for (int hf = 0; hf < 2; hf++) {
            const float inv = 1.0f / l[im][hf];
            const long long row = (long long)b * TSEQ + q0 + wm + im * 16 + hf * 8 + lr;
            #pragma unroll
            for (int jn = 0; jn < 8; jn++) {
                *(half2*)(ycat + row * EDIM + h * HD + jn * 8 + 2 * lc) =
                    __floats2half2_rn(o[im][jn][hf * 2] * inv, o[im][jn][hf * 2 + 1] * inv);
            }
        }
    }
}

// ---------------------------------------------------------------------------
// fp16 GEMM: 128x256 CTA tile, 8 warps x (64x64), GBK=32, 4-stage cp.async.
// Single-buffered fragments per k16-slice (8 ldmatrix : 32 MMA).
// EPI: 1 +bias, 2 +bias,GELU, 3 +bias,+res(fp32). HOUT: fp16 C, else fp32.
// ---------------------------------------------------------------------------
#define GBM 128
#define GBN 256
#define GBK 32
#define GSTR 40                      // halves per smem row (32 + 8 pad)
#define STAGE_H ((GBM + GBN) * GSTR) // 15360 halves per stage
#define G_SMEM_B (4 * STAGE_H * 2)   // 122880 B

template <int EPI, bool HOUT>
__global__ void __launch_bounds__(256)
mma_gemm(int K,
         const __half* __restrict__ A, int lda,
         const __half* __restrict__ BT, int ldb,
         void* __restrict__ Cv, int ldc,
         const float* __restrict__ bias,
         const float* __restrict__ res) {
    extern __shared__ __half gsh[];
    const int m0 = blockIdx.y * GBM;
    const int n0 = blockIdx.x * GBN;
    const int tid  = threadIdx.x;
    const int lane = tid & 31;
    const int warp = tid >> 5;
    const int wm = (warp >> 2) * 64;     // 2 m-warps
    const int wn = (warp & 3) * 64;      // 4 n-warps, 64 wide
    const int lr = lane >> 2;
    const int lc = lane & 3;

    float acc[4][8][4];
    #pragma unroll
    for (int i = 0; i < 4; i++)
        #pragma unroll
        for (int j = 0; j < 8; j++)
            #pragma unroll
            for (int q = 0; q < 4; q++) acc[i][j][q] = 0.0f;

    const int KT = K / GBK;

    auto load_tile = [&](int kt, int st) {
        __half* As = gsh + st * STAGE_H;
        __half* Bs = gsh + st * STAGE_H + GBM * GSTR;
        const int k0 = kt * GBK;
        // A: 128 rows x 4 chunks; B: 256 rows x 4 chunks (each chunk 8 halves)
        #pragma unroll
        for (int i = tid; i < 512; i += 256) {
            int r = i >> 2, ch = (i & 3) << 3;
            cp_async16(As + r * GSTR + ch, A  + (long long)(m0 + r) * lda + k0 + ch);
        }
        #pragma unroll
        for (int i = tid; i < 1024; i += 256) {
            int r = i >> 2, ch = (i & 3) << 3;
            cp_async16(Bs + r * GSTR + ch, BT + (long long)(n0 + r) * ldb + k0 + ch);
        }
        cp_commit();
    };

    load_tile(0, 0);
    if (KT > 1) load_tile(1, 1);
    if (KT > 2) load_tile(2, 2);

    int st = 0;
    for (int kt = 0; kt < KT; kt++) {
        if (kt + 2 < KT)      cp_wait<2>();
        else if (kt + 1 < KT) cp_wait<1>();
        else                  cp_wait<0>();
        __syncthreads();
        if (kt + 3 < KT) {
            int st3 = st + 3; if (st3 >= 4) st3 -= 4;
            load_tile(kt + 3, st3);
        }
        const __half* As = gsh + st * STAGE_H;
        const __half* Bs = gsh + st * STAGE_H + GBM * GSTR;

        #pragma unroll
        for (int ks = 0; ks < 2; ks++) {
            const int kq = ks * 16;
            uint32_t afr[4][4];
            #pragma unroll
            for (int im = 0; im < 4; im++) {
                uint32_t sa = (uint32_t)__cvta_generic_to_shared(
                    As + (wm + im * 16 + (lane & 15)) * GSTR + kq + ((lane >> 4) << 3));
                ldmatrix_x4(afr[im][0], afr[im][1], afr[im][2], afr[im][3], sa);
            }
            uint32_t bfr[4][4];   // pair p covers jn=2p, 2p+1
            #pragma unroll
            for (int p = 0; p < 4; p++) {
                uint32_t sb = (uint32_t)__cvta_generic_to_shared(
                    Bs + (wn + p * 16 + (lane & 7) + ((lane >> 4) << 3)) * GSTR
                       + kq + (((lane >> 3) & 1) << 3));
                ldmatrix_x4(bfr[p][0], bfr[p][1], bfr[p][2], bfr[p][3], sb);
            }
            #pragma unroll
            for (int p = 0; p < 4; p++)
                #pragma unroll
                for (int im = 0; im < 4; im++) {
                    mma_f16(acc[im][2 * p],     afr[im], &bfr[p][0]);
                    mma_f16(acc[im][2 * p + 1], afr[im], &bfr[p][2]);
                }
        }
        __syncthreads();
        if (++st == 4) st = 0;
    }

    #pragma unroll
    for (int im = 0; im < 4; im++) {
        const int r0 = m0 + wm + im * 16 + lr;
        #pragma unroll
        for (int jn = 0; jn < 8; jn++) {
            const int cb = n0 + wn + jn * 8 + lc * 2;
            float bv0 = bias[cb], bv1 = bias[cb + 1];
            #pragma unroll
            for (int hf = 0; hf < 2; hf++) {
                const int r = r0 + hf * 8;
                float v0 = acc[im][jn][hf * 2]     + bv0;
                float v1 = acc[im][jn][hf * 2 + 1] + bv1;
                if (EPI == 2) { v0 = gelu_tanh(v0); v1 = gelu_tanh(v1); }
                if (EPI == 3) {
                    const float* rp = res + (long long)r * ldc + cb;
                    v0 += rp[0]; v1 += rp[1];
                }
                if (HOUT) {
                    *(half2*)((__half*)Cv + (long long)r * ldc + cb) =
                        __floats2half2_rn(v0, v1);
                } else {
                    float* cp = (float*)Cv + (long long)r * ldc + cb;
                    cp[0] = v0; cp[1] = v1;
                }
            }
        }
    }
}

// ---------------------------------------------------------------------------
extern "C" void kernel_launch(void* const* d_in, const int* in_sizes, int n_in,
                              void* d_out, int out_size) {
    const float* x     = (const float*)d_in[0];
    const float* ln1g  = (const float*)d_in[1];
    const float* ln1b  = (const float*)d_in[2];
    const float* Wqkv  = (const float*)d_in[3];
    const float* bqkv  = (const float*)d_in[4];
    const float* Wproj = (const float*)d_in[5];
    const float* bproj = (const float*)d_in[6];
    const float* ln2g  = (const float*)d_in[7];
    const float* ln2b  = (const float*)d_in[8];
    const float* Wfc   = (const float*)d_in[9];
    const float* bfc   = (const float*)d_in[10];
    const float* Wout  = (const float*)d_in[11];
    const float* bout  = (const float*)d_in[12];
    float* out = (float*)d_out;

    __half *xn, *qkv, *ycat, *hbuf, *wh;
    cudaGetSymbolAddress((void**)&xn,   g_xn);
    cudaGetSymbolAddress((void**)&qkv,  g_qkv);
    cudaGetSymbolAddress((void**)&ycat, g_ycat);
    cudaGetSymbolAddress((void**)&hbuf, g_h);
    cudaGetSymbolAddress((void**)&wh,   g_wh);

    const int gsmem = G_SMEM_B;                    // 122880 B
    const int fsmem = FL_SMEM_H * sizeof(__half);  // 110592 B
    static bool attr_done = false;
    if (!attr_done) {
        cudaFuncSetAttribute(mma_gemm<1,true >, cudaFuncAttributeMaxDynamicSharedMemorySize, gsmem);
        cudaFuncSetAttribute(mma_gemm<2,true >, cudaFuncAttributeMaxDynamicSharedMemorySize, gsmem);
        cudaFuncSetAttribute(mma_gemm<3,false>, cudaFuncAttributeMaxDynamicSharedMemorySize, gsmem);
        cudaFuncSetAttribute(flash_kernel, cudaFuncAttributeMaxDynamicSharedMemorySize, fsmem);
        attr_done = true;
    }

    // 0) transpose + fp16-convert weights: WT[n][k]
    transpose_half<<<dim3(3 * EDIM / 32, EDIM / 32), dim3(32, 8)>>>(Wqkv,  wh + WR_QKV,  EDIM, 3 * EDIM);
    transpose_half<<<dim3(EDIM / 32,     EDIM / 32), dim3(32, 8)>>>(Wproj, wh + WR_PROJ, EDIM, EDIM);
    transpose_half<<<dim3(HID / 32,      EDIM / 32), dim3(32, 8)>>>(Wfc,   wh + WR_FC,   EDIM, HID);
    transpose_half<<<dim3(EDIM / 32,     HID / 32),  dim3(32, 8)>>>(Wout,  wh + WR_OUT,  HID,  EDIM);

    // 1) LN1 -> fp16
    ln_kernel<<<RROWS, 256>>>(x, ln1g, ln1b, xn);

    // 2) QKV = LN1(x) @ Wqkv + bqkv  (fp16 out; feeds flash)
    mma_gemm<1,true><<<dim3(3 * EDIM / GBN, RROWS / GBM), 256, gsmem>>>(
        EDIM, xn, EDIM, wh + WR_QKV, EDIM, qkv, 3 * EDIM, bqkv, nullptr);

    // 3) flash attention -> ycat (fp16)
    flash_kernel<<<dim3(TSEQ / 256, HEADS, BATCH), 256, fsmem>>>(qkv, ycat);

    // 4) x1 = x + ycat @ Wproj + bproj -> d_out (fp32)
    mma_gemm<3,false><<<dim3(EDIM / GBN, RROWS / GBM), 256, gsmem>>>(
        EDIM, ycat, EDIM, wh + WR_PROJ, EDIM, out, EDIM, bproj, x);

    // 5) LN2(x1) -> fp16
    ln_kernel<<<RROWS, 256>>>(out, ln2g, ln2b, xn);

    // 6) h = gelu(xn @ Wfc + bfc)  (fp16 out)
    mma_gemm<2,true><<<dim3(HID / GBN, RROWS / GBM), 256, gsmem>>>(
        EDIM, xn, EDIM, wh + WR_FC, EDIM, hbuf, HID, bfc, nullptr);

    // 7) out = x1 + h @ Wout + bout (fp32)
    mma_gemm<3,false><<<dim3(EDIM / GBN, RROWS / GBM), 256, gsmem>>>(
        HID, hbuf, HID, wh + WR_OUT, HID, out, EDIM, bout, out);
}

// round 16
// speedup vs baseline: 1.7335x; 1.7335x over previous
#include <cuda_runtime.h>
#include <cuda_fp16.h>
#include <cstdint>

// ---------------------------------------------------------------------------
// TransformerBlock B=8,T=1024,E=1024,H=16,HD=64,HID=4096 fp32.
// R15: R13b per-warp GEMM structure (64x32 warp tile, GBK=64, pipelined
// fragments) scaled to a 128x256 CTA tile with 512 threads (16 warps,
// 2m x 8n). 165.9KB smem, 3-stage cp.async. Flash/LN/transpose = R13b.
// ---------------------------------------------------------------------------

#define RROWS 8192
#define EDIM  1024
#define HEADS 16
#define HD    64
#define HID   4096
#define TSEQ  1024
#define BATCH 8

__device__ __half g_xn  [RROWS * EDIM];
__device__ __half g_qkv [RROWS * 3 * EDIM];
__device__ __half g_ycat[RROWS * EDIM];
__device__ __half g_h   [RROWS * HID];
__device__ __half g_wh  [12582912];   // transposed fp16 weights

#define WR_QKV  0            // [3072][1024]
#define WR_PROJ 3145728      // [1024][1024]
#define WR_FC   4194304      // [4096][1024]
#define WR_OUT  8388608      // [1024][4096]

__device__ __forceinline__ float gelu_tanh(float x) {
    float x3 = x * x * x;
    return 0.5f * x * (1.0f + tanhf(0.7978845608028654f * (x + 0.044715f * x3)));
}
__device__ __forceinline__ void cp_async16(void* smem_dst, const void* gsrc) {
    uint32_t d = (uint32_t)__cvta_generic_to_shared(smem_dst);
    asm volatile("cp.async.cg.shared.global [%0], [%1], 16;\n" :: "r"(d), "l"(gsrc));
}
__device__ __forceinline__ void cp_commit() { asm volatile("cp.async.commit_group;\n"); }
template <int N>
__device__ __forceinline__ void cp_wait() { asm volatile("cp.async.wait_group %0;\n" :: "n"(N)); }

// m16n8k16 fp16 MMA, fp32 accumulate.
__device__ __forceinline__ void mma_f16(float* c, const uint32_t* a, const uint32_t* b) {
    asm volatile(
        "mma.sync.aligned.m16n8k16.row.col.f32.f16.f16.f32 "
        "{%0,%1,%2,%3}, {%4,%5,%6,%7}, {%8,%9}, {%0,%1,%2,%3};"
        : "+f"(c[0]), "+f"(c[1]), "+f"(c[2]), "+f"(c[3])
        : "r"(a[0]), "r"(a[1]), "r"(a[2]), "r"(a[3]), "r"(b[0]), "r"(b[1]));
}

__device__ __forceinline__ void ldmatrix_x4(uint32_t& r0, uint32_t& r1, uint32_t& r2,
                                            uint32_t& r3, uint32_t saddr) {
    asm volatile("ldmatrix.sync.aligned.m8n8.x4.shared.b16 {%0,%1,%2,%3}, [%4];"
                 : "=r"(r0), "=r"(r1), "=r"(r2), "=r"(r3) : "r"(saddr));
}
__device__ __forceinline__ void ldmatrix_x2(uint32_t& r0, uint32_t& r1, uint32_t saddr) {
    asm volatile("ldmatrix.sync.aligned.m8n8.x2.shared.b16 {%0,%1}, [%2];"
                 : "=r"(r0), "=r"(r1) : "r"(saddr));
}
__device__ __forceinline__ void ldmatrix_x2_trans(uint32_t& r0, uint32_t& r1, uint32_t saddr) {
    asm volatile("ldmatrix.sync.aligned.m8n8.x2.trans.shared.b16 {%0,%1}, [%2];"
                 : "=r"(r0), "=r"(r1) : "r"(saddr));
}

// ---------------------------------------------------------------------------
// Weight transpose + fp16 convert:  WT[n][k] = half(W[k][n]).  in: [K][N].
// ---------------------------------------------------------------------------
__global__ void transpose_half(const float* __restrict__ in, __half* __restrict__ outp,
                               int K, int N) {
    __shared__ float t[32][33];
    const int n0 = blockIdx.x * 32, k0 = blockIdx.y * 32;
    const int tx = threadIdx.x, ty = threadIdx.y;
    #pragma unroll
    for (int j = 0; j < 32; j += 8)
        t[ty + j][tx] = in[(long long)(k0 + ty + j) * N + n0 + tx];
    __syncthreads();
    #pragma unroll
    for (int j = 0; j < 32; j += 8)
        outp[(long long)(n0 + ty + j) * K + k0 + tx] = __float2half(t[tx][ty + j]);
}

// ---------------------------------------------------------------------------
// LayerNorm: one block (256 threads) per 1024-col row; fp32 in, fp16 out.
// ---------------------------------------------------------------------------
__global__ void ln_kernel(const float* __restrict__ x,
                          const float* __restrict__ g,
                          const float* __restrict__ b,
                          __half* __restrict__ out) {
    __shared__ float red[8];
    const long long row = blockIdx.x;
    const int t = threadIdx.x;
    float4 v = ((const float4*)(x + row * EDIM))[t];

    float s = v.x + v.y + v.z + v.w;
    #pragma unroll
    for (int o = 16; o; o >>= 1) s += __shfl_xor_sync(~0u, s, o);
    if ((t & 31) == 0) red[t >> 5] = s;
    __syncthreads();
    if (t < 8) {
        s = red[t];
        #pragma unroll
        for (int o = 4; o; o >>= 1) s += __shfl_xor_sync(0xffu, s, o);
        if (t == 0) red[0] = s;
    }
    __syncthreads();
    const float mean = red[0] * (1.0f / EDIM);

    float dx = v.x - mean, dy = v.y - mean, dz = v.z - mean, dw = v.w - mean;
    float q = dx * dx + dy * dy + dz * dz + dw * dw;
    #pragma unroll
    for (int o = 16; o; o >>= 1) q += __shfl_xor_sync(~0u, q, o);
    __syncthreads();
    if ((t & 31) == 0) red[t >> 5] = q;
    __syncthreads();
    if (t < 8) {
        q = red[t];
        #pragma unroll
        for (int o = 4; o; o >>= 1) q += __shfl_xor_sync(0xffu, q, o);
        if (t == 0) red[0] = q;
    }
    __syncthreads();
    const float rstd = rsqrtf(red[0] * (1.0f / EDIM) + 1e-5f);

    const float4 gg = ((const float4*)g)[t];
    const float4 bb = ((const float4*)b)[t];
    half2 h0 = __floats2half2_rn(dx * rstd * gg.x + bb.x, dy * rstd * gg.y + bb.y);
    half2 h1 = __floats2half2_rn(dz * rstd * gg.z + bb.z, dw * rstd * gg.w + bb.w);
    half2* op = (half2*)(out + row * EDIM + t * 4);
    op[0] = h0; op[1] = h1;
}

// ---------------------------------------------------------------------------
// Flash attention fp16, non-causal — unchanged from R13b.
// ---------------------------------------------------------------------------
#define QSTR 72   // halves per row (64 + 8 pad)
#define FL_QOFF 0
#define FL_KOFF (256 * QSTR)
#define FL_VOFF (FL_KOFF + 2 * 64 * QSTR)
#define FL_POFF (FL_VOFF + 2 * 64 * QSTR)
#define FL_SMEM_H (FL_POFF + 256 * QSTR)

__global__ void __launch_bounds__(256)
flash_kernel(const __half* __restrict__ qkv, __half* __restrict__ ycat) {
    extern __shared__ __half sh[];
    __half* Qsm = sh + FL_QOFF;
    __half* Psm = sh + FL_POFF;

    const int tid  = threadIdx.x;
    const int lane = tid & 31;
    const int warp = tid >> 5;
    const int lr = lane >> 2;
    const int lc = lane & 3;
    const int q0 = blockIdx.x * 256;
    const int h  = blockIdx.y;
    const int b  = blockIdx.z;
    const int wm = warp * 32;

    const __half* qkvb = qkv + (long long)b * TSEQ * 3 * EDIM;
    const __half* Qg = qkvb + h * HD;
    const __half* Kg = qkvb + EDIM + h * HD;
    const __half* Vg = qkvb + 2 * EDIM + h * HD;

    const half2 qsc = __floats2half2_rn(0.125f, 0.125f);
    #pragma unroll
    for (int i = tid; i < 256 * 8; i += 256) {
        int r = i >> 3, ch = (i & 7) << 3;
        uint4 v = *(const uint4*)(Qg + (long long)(q0 + r) * 3 * EDIM + ch);
        half2* hv = (half2*)&v;
        hv[0] = __hmul2(hv[0], qsc); hv[1] = __hmul2(hv[1], qsc);
        hv[2] = __hmul2(hv[2], qsc); hv[3] = __hmul2(hv[3], qsc);
        *(uint4*)(Qsm + r * QSTR + ch) = v;
    }

    auto load_kv = [&](int j, int buf) {
        __half* Ks = sh + FL_KOFF + buf * 64 * QSTR;
        __half* Vs = sh + FL_VOFF + buf * 64 * QSTR;
        const __half* Kj = Kg + (long long)(j * 64) * 3 * EDIM;
        const __half* Vj = Vg + (long long)(j * 64) * 3 * EDIM;
        #pragma unroll
        for (int i = tid; i < 64 * 8; i += 256) {
            int r = i >> 3, ch = (i & 7) << 3;
            cp_async16(Ks + r * QSTR + ch, Kj + (long long)r * 3 * EDIM + ch);
            cp_async16(Vs + r * QSTR + ch, Vj + (long long)r * 3 * EDIM + ch);
        }
        cp_commit();
    };

    load_kv(0, 0);
    __syncthreads();

    uint32_t qfr[4][2][4];
    #pragma unroll
    for (int ks = 0; ks < 4; ks++) {
        #pragma unroll
        for (int im = 0; im < 2; im++) {
            uint32_t sa = (uint32_t)__cvta_generic_to_shared(
                Qsm + (wm + im * 16 + (lane & 15)) * QSTR + ks * 16 + ((lane >> 4) << 3));
            ldmatrix_x4(qfr[ks][im][0], qfr[ks][im][1], qfr[ks][im][2], qfr[ks][im][3], sa);
        }
    }

    float o[2][8][4];
    float m[2][2], l[2][2];
    #pragma unroll
    for (int im = 0; im < 2; im++) {
        #pragma unroll
        for (int jn = 0; jn < 8; jn++)
            #pragma unroll
            for (int q = 0; q < 4; q++) o[im][jn][q] = 0.0f;
        m[im][0] = m[im][1] = -1e30f;
        l[im][0] = l[im][1] = 0.0f;
    }

    const int NT = TSEQ / 64;
    for (int j = 0; j < NT; j++) {
        const int buf = j & 1;
        if (j + 1 < NT) { load_kv(j + 1, buf ^ 1); cp_wait<1>(); }
        else           { cp_wait<0>(); }
        __syncthreads();

        const __half* Ks = sh + FL_KOFF + buf * 64 * QSTR;
        const __half* Vs = sh + FL_VOFF + buf * 64 * QSTR;

        float s[2][8][4];
        #pragma unroll
        for (int im = 0; im < 2; im++)
            #pragma unroll
            for (int jn = 0; jn < 8; jn++)
                #pragma unroll
                for (int q = 0; q < 4; q++) s[im][jn][q] = 0.0f;

        #pragma unroll
        for (int ks = 0; ks < 4; ks++) {
            #pragma unroll
            for (int jn = 0; jn < 8; jn++) {
                uint32_t bfr[2];
                uint32_t sb = (uint32_t)__cvta_generic_to_shared(
                    Ks + (jn * 8 + (lane & 7)) * QSTR + ks * 16 + (((lane >> 3) & 3) == 1 ? 8 : 0));
                ldmatrix_x2(bfr[0], bfr[1], sb);
                #pragma unroll
                for (int im = 0; im < 2; im++) mma_f16(s[im][jn], qfr[ks][im], bfr);
            }
        }

        #pragma unroll
        for (int im = 0; im < 2; im++) {
            #pragma unroll
            for (int hf = 0; hf < 2; hf++) {
                float mx = -1e30f;
                #pragma unroll
                for (int jn = 0; jn < 8; jn++)
                    mx = fmaxf(mx, fmaxf(s[im][jn][hf * 2], s[im][jn][hf * 2 + 1]));
                mx = fmaxf(mx, __shfl_xor_sync(~0u, mx, 1));
                mx = fmaxf(mx, __shfl_xor_sync(~0u, mx, 2));
                const float mnew = fmaxf(m[im][hf], mx);
                const float alpha = __expf(m[im][hf] - mnew);
                m[im][hf] = mnew;
                const int prow = wm + im * 16 + hf * 8 + lr;
                float sum = 0.0f;
                #pragma unroll
                for (int jn = 0; jn < 8; jn++) {
                    float p0 = __expf(s[im][jn][hf * 2]     - mnew);
                    float p1 = __expf(s[im][jn][hf * 2 + 1] - mnew);
                    sum += p0 + p1;
                    *(half2*)(Psm + prow * QSTR + jn * 8 + 2 * lc) = __floats2half2_rn(p0, p1);
                }
                sum += __shfl_xor_sync(~0u, sum, 1);
                sum += __shfl_xor_sync(~0u, sum, 2);
                l[im][hf] = l[im][hf] * alpha + sum;
                #pragma unroll
                for (int jn = 0; jn < 8; jn++) {
                    o[im][jn][hf * 2]     *= alpha;
                    o[im][jn][hf * 2 + 1] *= alpha;
                }
            }
        }
        __syncwarp();

        #pragma unroll
        for (int ks = 0; ks < 4; ks++) {
            uint32_t afr[2][4];
            #pragma unroll
            for (int im = 0; im < 2; im++) {
                uint32_t sa = (uint32_t)__cvta_generic_to_shared(
                    Psm + (wm + im * 16 + (lane & 15)) * QSTR + ks * 16 + ((lane >> 4) << 3));
                ldmatrix_x4(afr[im][0], afr[im][1], afr[im][2], afr[im][3], sa);
            }
            #pragma unroll
            for (int jn = 0; jn < 8; jn++) {
                uint32_t bfr[2];
                uint32_t sv = (uint32_t)__cvta_generic_to_shared(
                    Vs + (ks * 16 + (lane & 15)) * QSTR + jn * 8);
                ldmatrix_x2_trans(bfr[0], bfr[1], sv);
                #pragma unroll
                for (int im = 0; im < 2; im++) mma_f16(o[im][jn], afr[im], bfr);
            }
        }
        __syncthreads();
    }

    #pragma unroll
    for (int im = 0; im < 2; im++) {
        #pragma unroll
        for (int hf = 0; hf < 2; hf++) {
            const float inv = 1.0f / l[im][hf];
            const long long row = (long long)b * TSEQ + q0 + wm + im * 16 + hf * 8 + lr;
            #pragma unroll
            for (int jn = 0; jn < 8; jn++) {
                *(half2*)(ycat + row * EDIM + h * HD + jn * 8 + 2 * lc) =
                    __floats2half2_rn(o[im][jn][hf * 2] * inv, o[im][jn][hf * 2 + 1] * inv);
            }
        }
    }
}

// ---------------------------------------------------------------------------
// fp16 GEMM: 128x256 CTA tile, 512 threads = 16 warps x (64x32), GBK=64,
// 3-stage cp.async, software-pipelined fragments (R13b inner loop).
// EPI: 1 +bias, 2 +bias,GELU, 3 +bias,+res(fp32). HOUT: fp16 C, else fp32.
// ---------------------------------------------------------------------------
#define GBM 128
#define GBN 256
#define GBK 64
#define GSTR 72                      // halves per smem row (64 + 8 pad)
#define STAGE_H ((GBM + GBN) * GSTR) // 27648 halves per stage
#define G_SMEM_B (3 * STAGE_H * 2)   // 165888 B

template <int EPI, bool HOUT>
__global__ void __launch_bounds__(512)
mma_gemm(int K,
         const __half* __restrict__ A, int lda,
         const __half* __restrict__ BT, int ldb,
         void* __restrict__ Cv, int ldc,
         const float* __restrict__ bias,
         const float* __restrict__ res) {
    extern __shared__ __half gsh[];
    const int m0 = blockIdx.y * GBM;
    const int n0 = blockIdx.x * GBN;
    const int tid  = threadIdx.x;
    const int lane = tid & 31;
    const int warp = tid >> 5;
    const int wm = (warp >> 3) * 64;     // 2 m-warps
    const int wn = (warp & 7) * 32;      // 8 n-warps
    const int lr = lane >> 2;
    const int lc = lane & 3;

    float acc[4][4][4];
    #pragma unroll
    for (int i = 0; i < 4; i++)
        #pragma unroll
        for (int j = 0; j < 4; j++)
            #pragma unroll
            for (int q = 0; q < 4; q++) acc[i][j][q] = 0.0f;

    const int KT = K / GBK;

    auto load_tile = [&](int kt, int st) {
        __half* As = gsh + st * STAGE_H;
        __half* Bs = gsh + st * STAGE_H + GBM * GSTR;
        const int k0 = kt * GBK;
        // A: 128 rows x 8 chunks = 1024; B: 256 rows x 8 chunks = 2048
        #pragma unroll
        for (int i = tid; i < 1024; i += 512) {
            int r = i >> 3, ch = (i & 7) << 3;
            cp_async16(As + r * GSTR + ch, A  + (long long)(m0 + r) * lda + k0 + ch);
        }
        #pragma unroll
        for (int i = tid; i < 2048; i += 512) {
            int r = i >> 3, ch = (i & 7) << 3;
            cp_async16(Bs + r * GSTR + ch, BT + (long long)(n0 + r) * ldb + k0 + ch);
        }
        cp_commit();
    };

    // Fragment buffers (double-buffered across k-slices).
    uint32_t afr[2][4][4];   // [buf][im][regs]
    uint32_t bfr[2][2][4];   // [buf][pair][regs]: pair p covers jn=2p,2p+1

    auto ld_frag = [&](const __half* As, const __half* Bs, int ks, int buf) {
        const int kq = ks * 16;
        #pragma unroll
        for (int im = 0; im < 4; im++) {
            uint32_t sa = (uint32_t)__cvta_generic_to_shared(
                As + (wm + im * 16 + (lane & 15)) * GSTR + kq + ((lane >> 4) << 3));
            ldmatrix_x4(afr[buf][im][0], afr[buf][im][1], afr[buf][im][2], afr[buf][im][3], sa);
        }
        #pragma unroll
        for (int p = 0; p < 2; p++) {
            uint32_t sb = (uint32_t)__cvta_generic_to_shared(
                Bs + (wn + p * 16 + (lane & 7) + ((lane >> 4) << 3)) * GSTR
                   + kq + (((lane >> 3) & 1) << 3));
            ldmatrix_x4(bfr[buf][p][0], bfr[buf][p][1], bfr[buf][p][2], bfr[buf][p][3], sb);
        }
    };

    load_tile(0, 0);
    if (KT > 1) load_tile(1, 1);

    int st = 0;
    for (int kt = 0; kt < KT; kt++) {
        if (kt + 1 < KT) cp_wait<1>(); else cp_wait<0>();
        __syncthreads();
        if (kt + 2 < KT) {
            int st2 = st + 2; if (st2 >= 3) st2 -= 3;
            load_tile(kt + 2, st2);
        }
        const __half* As = gsh + st * STAGE_H;
        const __half* Bs = gsh + st * STAGE_H + GBM * GSTR;

        ld_frag(As, Bs, 0, 0);
        #pragma unroll
        for (int ks = 0; ks < 4; ks++) {
            const int cur = ks & 1;
            if (ks < 3) ld_frag(As, Bs, ks + 1, cur ^ 1);
            #pragma unroll
            for (int p = 0; p < 2; p++)
                #pragma unroll
                for (int im = 0; im < 4; im++) {
                    mma_f16(acc[im][2 * p],     afr[cur][im], &bfr[cur][p][0]);
                    mma_f16(acc[im][2 * p + 1], afr[cur][im], &bfr[cur][p][2]);
                }
        }
        __syncthreads();
        if (++st == 3) st = 0;
    }

    #pragma unroll
    for (int im = 0; im < 4; im++) {
        const int r0 = m0 + wm + im * 16 + lr;
        #pragma unroll
        for (int jn = 0; jn < 4; jn++) {
            const int cb = n0 + wn + jn * 8 + lc * 2;
            float bv0 = bias[cb], bv1 = bias[cb + 1];
            #pragma unroll
            for (int hf = 0; hf < 2; hf++) {
                const int r = r0 + hf * 8;
                float v0 = acc[im][jn][hf * 2]     + bv0;
                float v1 = acc[im][jn][hf * 2 + 1] + bv1;
                if (EPI == 2) { v0 = gelu_tanh(v0); v1 = gelu_tanh(v1); }
                if (EPI == 3) {
                    const float* rp = res + (long long)r * ldc + cb;
                    v0 += rp[0]; v1 += rp[1];
                }
                if (HOUT) {
                    *(half2*)((__half*)Cv + (long long)r * ldc + cb) =
                        __floats2half2_rn(v0, v1);
                } else {
                    float* cp = (float*)Cv + (long long)r * ldc + cb;
                    cp[0] = v0; cp[1] = v1;
                }
            }
        }
    }
}

// ---------------------------------------------------------------------------
extern "C" void kernel_launch(void* const* d_in, const int* in_sizes, int n_in,
                              void* d_out, int out_size) {
    const float* x     = (const float*)d_in[0];
    const float* ln1g  = (const float*)d_in[1];
    const float* ln1b  = (const float*)d_in[2];
    const float* Wqkv  = (const float*)d_in[3];
    const float* bqkv  = (const float*)d_in[4];
    const float* Wproj = (const float*)d_in[5];
    const float* bproj = (const float*)d_in[6];
    const float* ln2g  = (const float*)d_in[7];
    const float* ln2b  = (const float*)d_in[8];
    const float* Wfc   = (const float*)d_in[9];
    const float* bfc   = (const float*)d_in[10];
    const float* Wout  = (const float*)d_in[11];
    const float* bout  = (const float*)d_in[12];
    float* out = (float*)d_out;

    __half *xn, *qkv, *ycat, *hbuf, *wh;
    cudaGetSymbolAddress((void**)&xn,   g_xn);
    cudaGetSymbolAddress((void**)&qkv,  g_qkv);
    cudaGetSymbolAddress((void**)&ycat, g_ycat);
    cudaGetSymbolAddress((void**)&hbuf, g_h);
    cudaGetSymbolAddress((void**)&wh,   g_wh);

    const int gsmem = G_SMEM_B;                    // 165888 B
    const int fsmem = FL_SMEM_H * sizeof(__half);  // 110592 B
    static bool attr_done = false;
    if (!attr_done) {
        cudaFuncSetAttribute(mma_gemm<1,true >, cudaFuncAttributeMaxDynamicSharedMemorySize, gsmem);
        cudaFuncSetAttribute(mma_gemm<2,true >, cudaFuncAttributeMaxDynamicSharedMemorySize, gsmem);
        cudaFuncSetAttribute(mma_gemm<3,false>, cudaFuncAttributeMaxDynamicSharedMemorySize, gsmem);
        cudaFuncSetAttribute(flash_kernel, cudaFuncAttributeMaxDynamicSharedMemorySize, fsmem);
        attr_done = true;
    }

    // 0) transpose + fp16-convert weights: WT[n][k]
    transpose_half<<<dim3(3 * EDIM / 32, EDIM / 32), dim3(32, 8)>>>(Wqkv,  wh + WR_QKV,  EDIM, 3 * EDIM);
    transpose_half<<<dim3(EDIM / 32,     EDIM / 32), dim3(32, 8)>>>(Wproj, wh + WR_PROJ, EDIM, EDIM);
    transpose_half<<<dim3(HID / 32,      EDIM / 32), dim3(32, 8)>>>(Wfc,   wh + WR_FC,   EDIM, HID);
    transpose_half<<<dim3(EDIM / 32,     HID / 32),  dim3(32, 8)>>>(Wout,  wh + WR_OUT,  HID,  EDIM);

    // 1) LN1 -> fp16
    ln_kernel<<<RROWS, 256>>>(x, ln1g, ln1b, xn);

    // 2) QKV = LN1(x) @ Wqkv + bqkv  (fp16 out; feeds flash)
    mma_gemm<1,true><<<dim3(3 * EDIM / GBN, RROWS / GBM), 512, gsmem>>>(
        EDIM, xn, EDIM, wh + WR_QKV, EDIM, qkv, 3 * EDIM, bqkv, nullptr);

    // 3) flash attention -> ycat (fp16)
    flash_kernel<<<dim3(TSEQ / 256, HEADS, BATCH), 256, fsmem>>>(qkv, ycat);

    // 4) x1 = x + ycat @ Wproj + bproj -> d_out (fp32)
    mma_gemm<3,false><<<dim3(EDIM / GBN, RROWS / GBM), 512, gsmem>>>(
        EDIM, ycat, EDIM, wh + WR_PROJ, EDIM, out, EDIM, bproj, x);

    // 5) LN2(x1) -> fp16
    ln_kernel<<<RROWS, 256>>>(out, ln2g, ln2b, xn);

    // 6) h = gelu(xn @ Wfc + bfc)  (fp16 out)
    mma_gemm<2,true><<<dim3(HID / GBN, RROWS / GBM), 512, gsmem>>>(
        EDIM, xn, EDIM, wh + WR_FC, EDIM, hbuf, HID, bfc, nullptr);

    // 7) out = x1 + h @ Wout + bout (fp32)
    mma_gemm<3,false><<<dim3(EDIM / GBN, RROWS / GBM), 512, gsmem>>>(
        HID, hbuf, HID, wh + WR_OUT, HID, out, EDIM, bout, out);
}

// round 17
// speedup vs baseline: 1.8509x; 1.0677x over previous
#include <cuda_runtime.h>
#include <cuda_fp16.h>
#include <cstdint>

// ---------------------------------------------------------------------------
// TransformerBlock B=8,T=1024,E=1024,H=16,HD=64,HID=4096 fp32.
// R16: GEMM = exact R13b (128x128x64, 8 warps x 64x32, pipelined ldmatrix
// fragments, 3-stage cp.async). Flash: P kept in registers (FA2-style
// accumulator->A-fragment conversion) — no Psm, no P ldmatrix.
// ---------------------------------------------------------------------------

#define RROWS 8192
#define EDIM  1024
#define HEADS 16
#define HD    64
#define HID   4096
#define TSEQ  1024
#define BATCH 8

__device__ __half g_xn  [RROWS * EDIM];
__device__ __half g_qkv [RROWS * 3 * EDIM];
__device__ __half g_ycat[RROWS * EDIM];
__device__ __half g_h   [RROWS * HID];
__device__ __half g_wh  [12582912];   // transposed fp16 weights

#define WR_QKV  0            // [3072][1024]
#define WR_PROJ 3145728      // [1024][1024]
#define WR_FC   4194304      // [4096][1024]
#define WR_OUT  8388608      // [1024][4096]

__device__ __forceinline__ float gelu_tanh(float x) {
    float x3 = x * x * x;
    return 0.5f * x * (1.0f + tanhf(0.7978845608028654f * (x + 0.044715f * x3)));
}
__device__ __forceinline__ void cp_async16(void* smem_dst, const void* gsrc) {
    uint32_t d = (uint32_t)__cvta_generic_to_shared(smem_dst);
    asm volatile("cp.async.cg.shared.global [%0], [%1], 16;\n" :: "r"(d), "l"(gsrc));
}
__device__ __forceinline__ void cp_commit() { asm volatile("cp.async.commit_group;\n"); }
template <int N>
__device__ __forceinline__ void cp_wait() { asm volatile("cp.async.wait_group %0;\n" :: "n"(N)); }

// m16n8k16 fp16 MMA, fp32 accumulate.
__device__ __forceinline__ void mma_f16(float* c, const uint32_t* a, const uint32_t* b) {
    asm volatile(
        "mma.sync.aligned.m16n8k16.row.col.f32.f16.f16.f32 "
        "{%0,%1,%2,%3}, {%4,%5,%6,%7}, {%8,%9}, {%0,%1,%2,%3};"
        : "+f"(c[0]), "+f"(c[1]), "+f"(c[2]), "+f"(c[3])
        : "r"(a[0]), "r"(a[1]), "r"(a[2]), "r"(a[3]), "r"(b[0]), "r"(b[1]));
}

__device__ __forceinline__ void ldmatrix_x4(uint32_t& r0, uint32_t& r1, uint32_t& r2,
                                            uint32_t& r3, uint32_t saddr) {
    asm volatile("ldmatrix.sync.aligned.m8n8.x4.shared.b16 {%0,%1,%2,%3}, [%4];"
                 : "=r"(r0), "=r"(r1), "=r"(r2), "=r"(r3) : "r"(saddr));
}
__device__ __forceinline__ void ldmatrix_x2(uint32_t& r0, uint32_t& r1, uint32_t saddr) {
    asm volatile("ldmatrix.sync.aligned.m8n8.x2.shared.b16 {%0,%1}, [%2];"
                 : "=r"(r0), "=r"(r1) : "r"(saddr));
}
__device__ __forceinline__ void ldmatrix_x2_trans(uint32_t& r0, uint32_t& r1, uint32_t saddr) {
    asm volatile("ldmatrix.sync.aligned.m8n8.x2.trans.shared.b16 {%0,%1}, [%2];"
                 : "=r"(r0), "=r"(r1) : "r"(saddr));
}

// ---------------------------------------------------------------------------
// Weight transpose + fp16 convert:  WT[n][k] = half(W[k][n]).  in: [K][N].
// ---------------------------------------------------------------------------
__global__ void transpose_half(const float* __restrict__ in, __half* __restrict__ outp,
                               int K, int N) {
    __shared__ float t[32][33];
    const int n0 = blockIdx.x * 32, k0 = blockIdx.y * 32;
    const int tx = threadIdx.x, ty = threadIdx.y;
    #pragma unroll
    for (int j = 0; j < 32; j += 8)
        t[ty + j][tx] = in[(long long)(k0 + ty + j) * N + n0 + tx];
    __syncthreads();
    #pragma unroll
    for (int j = 0; j < 32; j += 8)
        outp[(long long)(n0 + ty + j) * K + k0 + tx] = __float2half(t[tx][ty + j]);
}

// ---------------------------------------------------------------------------
// LayerNorm: one block (256 threads) per 1024-col row; fp32 in, fp16 out.
// ---------------------------------------------------------------------------
__global__ void ln_kernel(const float* __restrict__ x,
                          const float* __restrict__ g,
                          const float* __restrict__ b,
                          __half* __restrict__ out) {
    __shared__ float red[8];
    const long long row = blockIdx.x;
    const int t = threadIdx.x;
    float4 v = ((const float4*)(x + row * EDIM))[t];

    float s = v.x + v.y + v.z + v.w;
    #pragma unroll
    for (int o = 16; o; o >>= 1) s += __shfl_xor_sync(~0u, s, o);
    if ((t & 31) == 0) red[t >> 5] = s;
    __syncthreads();
    if (t < 8) {
        s = red[t];
        #pragma unroll
        for (int o = 4; o; o >>= 1) s += __shfl_xor_sync(0xffu, s, o);
        if (t == 0) red[0] = s;
    }
    __syncthreads();
    const float mean = red[0] * (1.0f / EDIM);

    float dx = v.x - mean, dy = v.y - mean, dz = v.z - mean, dw = v.w - mean;
    float q = dx * dx + dy * dy + dz * dz + dw * dw;
    #pragma unroll
    for (int o = 16; o; o >>= 1) q += __shfl_xor_sync(~0u, q, o);
    __syncthreads();
    if ((t & 31) == 0) red[t >> 5] = q;
    __syncthreads();
    if (t < 8) {
        q = red[t];
        #pragma unroll
        for (int o = 4; o; o >>= 1) q += __shfl_xor_sync(0xffu, q, o);
        if (t == 0) red[0] = q;
    }
    __syncthreads();
    const float rstd = rsqrtf(red[0] * (1.0f / EDIM) + 1e-5f);

    const float4 gg = ((const float4*)g)[t];
    const float4 bb = ((const float4*)b)[t];
    half2 h0 = __floats2half2_rn(dx * rstd * gg.x + bb.x, dy * rstd * gg.y + bb.y);
    half2 h1 = __floats2half2_rn(dz * rstd * gg.z + bb.z, dw * rstd * gg.w + bb.w);
    half2* op = (half2*)(out + row * EDIM + t * 4);
    op[0] = h0; op[1] = h1;
}

// ---------------------------------------------------------------------------
// Flash attention fp16, non-causal. CTA = 256 q-rows of one (b,h), 8 warps.
// Q fragments hoisted; P converted accumulator->A-fragment IN REGISTERS
// (no smem round-trip). V via ldmatrix.trans. Double-buffered K/V cp.async.
// ---------------------------------------------------------------------------
#define QSTR 72   // halves per row (64 + 8 pad)
#define FL_QOFF 0
#define FL_KOFF (256 * QSTR)
#define FL_VOFF (FL_KOFF + 2 * 64 * QSTR)
#define FL_SMEM_H (FL_VOFF + 2 * 64 * QSTR)

__global__ void __launch_bounds__(256)
flash_kernel(const __half* __restrict__ qkv, __half* __restrict__ ycat) {
    extern __shared__ __half sh[];
    __half* Qsm = sh + FL_QOFF;

    const int tid  = threadIdx.x;
    const int lane = tid & 31;
    const int warp = tid >> 5;
    const int lr = lane >> 2;
    const int lc = lane & 3;
    const int q0 = blockIdx.x * 256;
    const int h  = blockIdx.y;
    const int b  = blockIdx.z;
    const int wm = warp * 32;

    const __half* qkvb = qkv + (long long)b * TSEQ * 3 * EDIM;
    const __half* Qg = qkvb + h * HD;
    const __half* Kg = qkvb + EDIM + h * HD;
    const __half* Vg = qkvb + 2 * EDIM + h * HD;

    // Q tile into smem (scaled by 0.125 — exact exponent shift)
    const half2 qsc = __floats2half2_rn(0.125f, 0.125f);
    #pragma unroll
    for (int i = tid; i < 256 * 8; i += 256) {
        int r = i >> 3, ch = (i & 7) << 3;
        uint4 v = *(const uint4*)(Qg + (long long)(q0 + r) * 3 * EDIM + ch);
        half2* hv = (half2*)&v;
        hv[0] = __hmul2(hv[0], qsc); hv[1] = __hmul2(hv[1], qsc);
        hv[2] = __hmul2(hv[2], qsc); hv[3] = __hmul2(hv[3], qsc);
        *(uint4*)(Qsm + r * QSTR + ch) = v;
    }

    auto load_kv = [&](int j, int buf) {
        __half* Ks = sh + FL_KOFF + buf * 64 * QSTR;
        __half* Vs = sh + FL_VOFF + buf * 64 * QSTR;
        const __half* Kj = Kg + (long long)(j * 64) * 3 * EDIM;
        const __half* Vj = Vg + (long long)(j * 64) * 3 * EDIM;
        #pragma unroll
        for (int i = tid; i < 64 * 8; i += 256) {
            int r = i >> 3, ch = (i & 7) << 3;
            cp_async16(Ks + r * QSTR + ch, Kj + (long long)r * 3 * EDIM + ch);
            cp_async16(Vs + r * QSTR + ch, Vj + (long long)r * 3 * EDIM + ch);
        }
        cp_commit();
    };

    load_kv(0, 0);
    __syncthreads();   // Q smem ready for fragment hoist

    // Hoist Q fragments: qfr[kstep][im][4], reused for all KV tiles.
    uint32_t qfr[4][2][4];
    #pragma unroll
    for (int ks = 0; ks < 4; ks++) {
        #pragma unroll
        for (int im = 0; im < 2; im++) {
            uint32_t sa = (uint32_t)__cvta_generic_to_shared(
                Qsm + (wm + im * 16 + (lane & 15)) * QSTR + ks * 16 + ((lane >> 4) << 3));
            ldmatrix_x4(qfr[ks][im][0], qfr[ks][im][1], qfr[ks][im][2], qfr[ks][im][3], sa);
        }
    }

    float o[2][8][4];
    float m[2][2], l[2][2];
    #pragma unroll
    for (int im = 0; im < 2; im++) {
        #pragma unroll
        for (int jn = 0; jn < 8; jn++)
            #pragma unroll
            for (int q = 0; q < 4; q++) o[im][jn][q] = 0.0f;
        m[im][0] = m[im][1] = -1e30f;
        l[im][0] = l[im][1] = 0.0f;
    }

    const int NT = TSEQ / 64;
    for (int j = 0; j < NT; j++) {
        const int buf = j & 1;
        if (j + 1 < NT) { load_kv(j + 1, buf ^ 1); cp_wait<1>(); }
        else           { cp_wait<0>(); }
        __syncthreads();

        const __half* Ks = sh + FL_KOFF + buf * 64 * QSTR;
        const __half* Vs = sh + FL_VOFF + buf * 64 * QSTR;

        // ---- S = Q K^T ----
        float s[2][8][4];
        #pragma unroll
        for (int im = 0; im < 2; im++)
            #pragma unroll
            for (int jn = 0; jn < 8; jn++)
                #pragma unroll
                for (int q = 0; q < 4; q++) s[im][jn][q] = 0.0f;

        #pragma unroll
        for (int ks = 0; ks < 4; ks++) {
            #pragma unroll
            for (int jn = 0; jn < 8; jn++) {
                uint32_t bfr[2];
                uint32_t sb = (uint32_t)__cvta_generic_to_shared(
                    Ks + (jn * 8 + (lane & 7)) * QSTR + ks * 16 + (((lane >> 3) & 3) == 1 ? 8 : 0));
                ldmatrix_x2(bfr[0], bfr[1], sb);
                #pragma unroll
                for (int im = 0; im < 2; im++) mma_f16(s[im][jn], qfr[ks][im], bfr);
            }
        }

        // ---- online softmax; P stays in registers as fp16 pairs ----
        // pfr[im][jn][hf]: hf=0 -> (c0,c1) row lr; hf=1 -> (c2,c3) row lr+8
        uint32_t pfr[2][8][2];
        #pragma unroll
        for (int im = 0; im < 2; im++) {
            #pragma unroll
            for (int hf = 0; hf < 2; hf++) {
                float mx = -1e30f;
                #pragma unroll
                for (int jn = 0; jn < 8; jn++)
                    mx = fmaxf(mx, fmaxf(s[im][jn][hf * 2], s[im][jn][hf * 2 + 1]));
                mx = fmaxf(mx, __shfl_xor_sync(~0u, mx, 1));
                mx = fmaxf(mx, __shfl_xor_sync(~0u, mx, 2));
                const float mnew = fmaxf(m[im][hf], mx);
                const float alpha = __expf(m[im][hf] - mnew);
                m[im][hf] = mnew;
                float sum = 0.0f;
                #pragma unroll
                for (int jn = 0; jn < 8; jn++) {
                    float p0 = __expf(s[im][jn][hf * 2]     - mnew);
                    float p1 = __expf(s[im][jn][hf * 2 + 1] - mnew);
                    sum += p0 + p1;
                    half2 ph = __floats2half2_rn(p0, p1);
                    pfr[im][jn][hf] = *(uint32_t*)&ph;
                }
                sum += __shfl_xor_sync(~0u, sum, 1);
                sum += __shfl_xor_sync(~0u, sum, 2);
                l[im][hf] = l[im][hf] * alpha + sum;
                #pragma unroll
                for (int jn = 0; jn < 8; jn++) {
                    o[im][jn][hf * 2]     *= alpha;
                    o[im][jn][hf * 2 + 1] *= alpha;
                }
            }
        }

        // ---- O += P @ V  (P fragments direct from registers) ----
        #pragma unroll
        for (int ks = 0; ks < 4; ks++) {
            uint32_t afr[2][4];
            #pragma unroll
            for (int im = 0; im < 2; im++) {
                afr[im][0] = pfr[im][2 * ks][0];      // row lr,   keys 16ks+2lc..+1
                afr[im][1] = pfr[im][2 * ks][1];      // row lr+8, same keys
                afr[im][2] = pfr[im][2 * ks + 1][0];  // row lr,   keys 16ks+8+2lc..+1
                afr[im][3] = pfr[im][2 * ks + 1][1];  // row lr+8, same keys
            }
            #pragma unroll
            for (int jn = 0; jn < 8; jn++) {
                uint32_t bfr[2];
                uint32_t sv = (uint32_t)__cvta_generic_to_shared(
                    Vs + (ks * 16 + (lane & 15)) * QSTR + jn * 8);
                ldmatrix_x2_trans(bfr[0], bfr[1], sv);
                #pragma unroll
                for (int im = 0; im < 2; im++) mma_f16(o[im][jn], afr[im], bfr);
            }
        }
        __syncthreads();
    }

    // ycat (fp16; feeds Wproj GEMM)
    #pragma unroll
    for (int im = 0; im < 2; im++) {
        #pragma unroll
        for (int hf = 0; hf < 2; hf++) {
            const float inv = 1.0f / l[im][hf];
            const long long row = (long long)b * TSEQ + q0 + wm + im * 16 + hf * 8 + lr;
            #pragma unroll
            for (int jn = 0; jn < 8; jn++) {
                *(half2*)(ycat + row * EDIM + h * HD + jn * 8 + 2 * lc) =
                    __floats2half2_rn(o[im][jn][hf * 2] * inv, o[im][jn][hf * 2 + 1] * inv);
            }
        }
    }
}

// ---------------------------------------------------------------------------
// fp16 GEMM (exact R13b): 128x128x64 CTA tile, 8 warps x (64x32), 3-stage
// cp.async, software-pipelined fragments.
// EPI: 1 +bias, 2 +bias,GELU, 3 +bias,+res(fp32). HOUT: fp16 C, else fp32.
// ---------------------------------------------------------------------------
#define GBM 128
#define GBN 128
#define GBK 64
#define GSTR 72               // halves per smem row (64 + 8 pad)
#define TILE_H (128 * GSTR)
#define G_SMEM_B (3 * 2 * TILE_H * 2)

template <int EPI, bool HOUT>
__global__ void __launch_bounds__(256)
mma_gemm(int K,
         const __half* __restrict__ A, int lda,
         const __half* __restrict__ BT, int ldb,
         void* __restrict__ Cv, int ldc,
         const float* __restrict__ bias,
         const float* __restrict__ res) {
    extern __shared__ __half gsh[];
    const int m0 = blockIdx.y * GBM;
    const int n0 = blockIdx.x * GBN;
    const int tid  = threadIdx.x;
    const int lane = tid & 31;
    const int warp = tid >> 5;
    const int wm = (warp >> 2) * 64;     // 2 m-warps
    const int wn = (warp & 3) * 32;      // 4 n-warps
    const int lr = lane >> 2;
    const int lc = lane & 3;

    float acc[4][4][4];
    #pragma unroll
    for (int i = 0; i < 4; i++)
        #pragma unroll
        for (int j = 0; j < 4; j++)
            #pragma unroll
            for (int q = 0; q < 4; q++) acc[i][j][q] = 0.0f;

    const int KT = K / GBK;

    auto load_tile = [&](int kt, int st) {
        __half* As = gsh + st * 2 * TILE_H;
        __half* Bs = gsh + st * 2 * TILE_H + TILE_H;
        const int k0 = kt * GBK;
        #pragma unroll
        for (int i = tid; i < 1024; i += 256) {
            int r = i >> 3, ch = (i & 7) << 3;
            cp_async16(As + r * GSTR + ch, A  + (long long)(m0 + r) * lda + k0 + ch);
        }
        #pragma unroll
        for (int i = tid; i < 1024; i += 256) {
            int r = i >> 3, ch = (i & 7) << 3;
            cp_async16(Bs + r * GSTR + ch, BT + (long long)(n0 + r) * ldb + k0 + ch);
        }
        cp_commit();
    };

    // Fragment buffers (double-buffered across k-slices).
    uint32_t afr[2][4][4];   // [buf][im][regs]
    uint32_t bfr[2][2][4];   // [buf][pair][regs]: pair p covers jn=2p,2p+1

    auto ld_frag = [&](const __half* As, const __half* Bs, int ks, int buf) {
        const int kq = ks * 16;
        #pragma unroll
        for (int im = 0; im < 4; im++) {
            uint32_t sa = (uint32_t)__cvta_generic_to_shared(
                As + (wm + im * 16 + (lane & 15)) * GSTR + kq + ((lane >> 4) << 3));
            ldmatrix_x4(afr[buf][im][0], afr[buf][im][1], afr[buf][im][2], afr[buf][im][3], sa);
        }
        #pragma unroll
        for (int p = 0; p < 2; p++) {
            uint32_t sb = (uint32_t)__cvta_generic_to_shared(
                Bs + (wn + p * 16 + (lane & 7) + ((lane >> 4) << 3)) * GSTR
                   + kq + (((lane >> 3) & 1) << 3));
            ldmatrix_x4(bfr[buf][p][0], bfr[buf][p][1], bfr[buf][p][2], bfr[buf][p][3], sb);
        }
    };

    load_tile(0, 0);
    load_tile(1, 1);

    int st = 0;
    for (int kt = 0; kt < KT; kt++) {
        if (kt + 1 < KT) cp_wait<1>(); else cp_wait<0>();
        __syncthreads();
        if (kt + 2 < KT) {
            int st2 = st + 2; if (st2 >= 3) st2 -= 3;
            load_tile(kt + 2, st2);
        }
        const __half* As = gsh + st * 2 * TILE_H;
        const __half* Bs = gsh + st * 2 * TILE_H + TILE_H;

        ld_frag(As, Bs, 0, 0);
        #pragma unroll
        for (int ks = 0; ks < 4; ks++) {
            const int cur = ks & 1;
            if (ks < 3) ld_frag(As, Bs, ks + 1, cur ^ 1);
            #pragma unroll
            for (int p = 0; p < 2; p++)
                #pragma unroll
                for (int im = 0; im < 4; im++) {
                    mma_f16(acc[im][2 * p],     afr[cur][im], &bfr[cur][p][0]);
                    mma_f16(acc[im][2 * p + 1], afr[cur][im], &bfr[cur][p][2]);
                }
        }
        __syncthreads();
        if (++st == 3) st = 0;
    }

    #pragma unroll
    for (int im = 0; im < 4; im++) {
        const int r0 = m0 + wm + im * 16 + lr;
        #pragma unroll
        for (int jn = 0; jn < 4; jn++) {
            const int cb = n0 + wn + jn * 8 + lc * 2;
            float bv0 = bias[cb], bv1 = bias[cb + 1];
            #pragma unroll
            for (int hf = 0; hf < 2; hf++) {
                const int r = r0 + hf * 8;
                float v0 = acc[im][jn][hf * 2]     + bv0;
                float v1 = acc[im][jn][hf * 2 + 1] + bv1;
                if (EPI == 2) { v0 = gelu_tanh(v0); v1 = gelu_tanh(v1); }
                if (EPI == 3) {
                    const float* rp = res + (long long)r * ldc + cb;
                    v0 += rp[0]; v1 += rp[1];
                }
                if (HOUT) {
                    *(half2*)((__half*)Cv + (long long)r * ldc + cb) =
                        __floats2half2_rn(v0, v1);
                } else {
                    float* cp = (float*)Cv + (long long)r * ldc + cb;
                    cp[0] = v0; cp[1] = v1;
                }
            }
        }
    }
}

// ---------------------------------------------------------------------------
extern "C" void kernel_launch(void* const* d_in, const int* in_sizes, int n_in,
                              void* d_out, int out_size) {
    const float* x     = (const float*)d_in[0];
    const float* ln1g  = (const float*)d_in[1];
    const float* ln1b  = (const float*)d_in[2];
    const float* Wqkv  = (const float*)d_in[3];
    const float* bqkv  = (const float*)d_in[4];
    const float* Wproj = (const float*)d_in[5];
    const float* bproj = (const float*)d_in[6];
    const float* ln2g  = (const float*)d_in[7];
    const float* ln2b  = (const float*)d_in[8];
    const float* Wfc   = (const float*)d_in[9];
    const float* bfc   = (const float*)d_in[10];
    const float* Wout  = (const float*)d_in[11];
    const float* bout  = (const float*)d_in[12];
    float* out = (float*)d_out;

    __half *xn, *qkv, *ycat, *hbuf, *wh;
    cudaGetSymbolAddress((void**)&xn,   g_xn);
    cudaGetSymbolAddress((void**)&qkv,  g_qkv);
    cudaGetSymbolAddress((void**)&ycat, g_ycat);
    cudaGetSymbolAddress((void**)&hbuf, g_h);
    cudaGetSymbolAddress((void**)&wh,   g_wh);

    const int gsmem = G_SMEM_B;                    // 110592 B
    const int fsmem = FL_SMEM_H * sizeof(__half);  // 73728 B
    static bool attr_done = false;
    if (!attr_done) {
        cudaFuncSetAttribute(mma_gemm<1,true >, cudaFuncAttributeMaxDynamicSharedMemorySize, gsmem);
        cudaFuncSetAttribute(mma_gemm<2,true >, cudaFuncAttributeMaxDynamicSharedMemorySize, gsmem);
        cudaFuncSetAttribute(mma_gemm<3,false>, cudaFuncAttributeMaxDynamicSharedMemorySize, gsmem);
        cudaFuncSetAttribute(flash_kernel, cudaFuncAttributeMaxDynamicSharedMemorySize, fsmem);
        attr_done = true;
    }

    // 0) transpose + fp16-convert weights: WT[n][k]
    transpose_half<<<dim3(3 * EDIM / 32, EDIM / 32), dim3(32, 8)>>>(Wqkv,  wh + WR_QKV,  EDIM, 3 * EDIM);
    transpose_half<<<dim3(EDIM / 32,     EDIM / 32), dim3(32, 8)>>>(Wproj, wh + WR_PROJ, EDIM, EDIM);
    transpose_half<<<dim3(HID / 32,      EDIM / 32), dim3(32, 8)>>>(Wfc,   wh + WR_FC,   EDIM, HID);
    transpose_half<<<dim3(EDIM / 32,     HID / 32),  dim3(32, 8)>>>(Wout,  wh + WR_OUT,  HID,  EDIM);

    // 1) LN1 -> fp16
    ln_kernel<<<RROWS, 256>>>(x, ln1g, ln1b, xn);

    // 2) QKV = LN1(x) @ Wqkv + bqkv  (fp16 out; feeds flash)
    mma_gemm<1,true><<<dim3(3 * EDIM / GBN, RROWS / GBM), 256, gsmem>>>(
        EDIM, xn, EDIM, wh + WR_QKV, EDIM, qkv, 3 * EDIM, bqkv, nullptr);

    // 3) flash attention -> ycat (fp16)
    flash_kernel<<<dim3(TSEQ / 256, HEADS, BATCH), 256, fsmem>>>(qkv, ycat);

    // 4) x1 = x + ycat @ Wproj + bproj -> d_out (fp32)
    mma_gemm<3,false><<<dim3(EDIM / GBN, RROWS / GBM), 256, gsmem>>>(
        EDIM, ycat, EDIM, wh + WR_PROJ, EDIM, out, EDIM, bproj, x);

    // 5) LN2(x1) -> fp16
    ln_kernel<<<RROWS, 256>>>(out, ln2g, ln2b, xn);

    // 6) h = gelu(xn @ Wfc + bfc)  (fp16 out)
    mma_gemm<2,true><<<dim3(HID / GBN, RROWS / GBM), 256, gsmem>>>(
        EDIM, xn, EDIM, wh + WR_FC, EDIM, hbuf, HID, bfc, nullptr);

    // 7) out = x1 + h @ Wout + bout (fp32)
    mma_gemm<3,false><<<dim3(EDIM / GBN, RROWS / GBM), 256, gsmem>>>(
        HID, hbuf, HID, wh + WR_OUT, HID, out, EDIM, bout, out);
}